// round 11
// baseline (speedup 1.0000x reference)
#include <cuda_runtime.h>
#include <cuda_fp16.h>
#include <cstdint>

#define NN 4096
#define MM 4096
#define DTC 0.01f

__device__ __half g_Kh[(size_t)NN * MM];

#define HR_WORDS (NN + 256)
__device__ __align__(16) uint32_t g_hr[HR_WORDS];

__global__ void exp_kernel(const float* __restrict__ x) {
    size_t p = (size_t)blockIdx.x * blockDim.x + threadIdx.x;
    const float4* x4 = (const float4*)x;
    float4 v0 = x4[p];
    float4 v1 = x4[p + 2097152];
    __half2 a0 = __floats2half2_rn(expf(-v0.x), expf(-v0.y));
    __half2 b0 = __floats2half2_rn(expf(-v0.z), expf(-v0.w));
    __half2 a1 = __floats2half2_rn(expf(-v1.x), expf(-v1.y));
    __half2 b1 = __floats2half2_rn(expf(-v1.z), expf(-v1.w));
    uint2 w0, w1;
    w0.x = *(uint32_t*)&a0; w0.y = *(uint32_t*)&b0;
    w1.x = *(uint32_t*)&a1; w1.y = *(uint32_t*)&b1;
    ((uint2*)g_Kh)[p] = w0;
    ((uint2*)g_Kh)[p + 2097152] = w1;
}

// g_hr[v] = (h[NN-1-v], h[NN-2-v]) as half2; zero-padded past the end (causal mask)
__global__ void pack_hr_kernel(const float* __restrict__ h) {
    int v = blockIdx.x * blockDim.x + threadIdx.x;
    if (v >= HR_WORDS) return;
    float e0 = (v < NN)     ? h[NN - 1 - v] : 0.f;
    float e1 = (v + 1 < NN) ? h[NN - 2 - v] : 0.f;
    __half2 p = __floats2half2_rn(e0, e1);
    g_hr[v] = *(uint32_t*)&p;
}

// ---------------- smem layout ----------------
#define SM_B_OFF (HR_WORDS * 4)        // 17408 bytes
#define B_STRIDE 272                   // 128 halfs + 8 pad
#define KC 64                          // K-chunk
#define STAGE_B  (KC * B_STRIDE)       // 17408
#define NSTAGE   4
#define SMEM_TOTAL (SM_B_OFF + NSTAGE * STAGE_B)   // 87040

#define NCTA 296                        // 2 x 148 SMs
#define NTILES 1024

__device__ __forceinline__ uint32_t smem_u32(const void* p) {
    return (uint32_t)__cvta_generic_to_shared(p);
}
__device__ __forceinline__ void cp16(uint32_t dst, const void* src) {
    asm volatile("cp.async.cg.shared.global [%0], [%1], 16;" :: "r"(dst), "l"(src) : "memory");
}
#define CP_COMMIT() asm volatile("cp.async.commit_group;" ::: "memory")
#define CP_WAIT2()  asm volatile("cp.async.wait_group 2;" ::: "memory")

__device__ __forceinline__ void ldmat_x4_t(uint32_t* r, uint32_t addr) {
    asm volatile("ldmatrix.sync.aligned.m8n8.x4.trans.shared.b16 {%0,%1,%2,%3}, [%4];"
                 : "=r"(r[0]), "=r"(r[1]), "=r"(r[2]), "=r"(r[3]) : "r"(addr));
}
__device__ __forceinline__ void mma16816(float* c, const uint32_t* a, const uint32_t* b) {
    asm volatile("mma.sync.aligned.m16n8k16.row.col.f32.f16.f16.f32 "
                 "{%0,%1,%2,%3}, {%4,%5,%6,%7}, {%8,%9}, {%0,%1,%2,%3};"
                 : "+f"(c[0]), "+f"(c[1]), "+f"(c[2]), "+f"(c[3])
                 : "r"(a[0]), "r"(a[1]), "r"(a[2]), "r"(a[3]), "r"(b[0]), "r"(b[1]));
}

// Persistent CTAs: 296 CTAs, each owns up to 4 tiles (snake assignment over
// j-descending tile list). One flattened cp.async pipeline spans tile boundaries.
// CTA tile 128(j) x 128(i), 8 warps of 64(j) x 32(i). K-chunk 64.
__global__ __launch_bounds__(256, 2) void memint_mma(
    const float* __restrict__ fe,
    const float* __restrict__ h,
    float* __restrict__ out)
{
    extern __shared__ char smem[];
    const uint32_t sbase = smem_u32(smem);
    uint32_t* hr = (uint32_t*)smem;

    const int tid  = threadIdx.x;
    const int lane = tid & 31;
    const int wid  = tid >> 5;
    const int wy   = wid & 1;       // j half (64)
    const int wx   = wid >> 1;      // i quarter (32)
    const int bid  = blockIdx.x;

    // ---- tile list (snake over j-descending order) ----
    int t_i0[4], t_j0[4], t_nT[4];
    int ntl = 0;
    #pragma unroll
    for (int r = 0; r < 4; r++) {
        int ctr = (r & 1) ? ((r + 1) * NCTA - 1 - bid) : (r * NCTA + bid);
        if (ctr < NTILES) {
            int jt_ord = ctr >> 5;
            t_j0[ntl] = (31 - jt_ord) * 128;
            t_i0[ntl] = (ctr & 31) * 128;
            t_nT[ntl] = 2 * (31 - jt_ord) + 2;
            ntl++;
        }
    }
    int T_tot = 0;
    #pragma unroll
    for (int k = 0; k < 4; k++) if (k < ntl) T_tot += t_nT[k];

    auto issue_one = [&](int i0t, int l0, int stage) {
        const uint32_t bs = sbase + SM_B_OFF + (uint32_t)stage * STAGE_B;
        #pragma unroll
        for (int k = 0; k < 4; k++) {
            int m = tid + k * 256;       // 1024 16B segments
            int row = m >> 4;            // l row 0..63
            int seg = m & 15;
            cp16(bs + (uint32_t)(row * B_STRIDE + seg * 16),
                 &g_Kh[(size_t)(l0 + row) * MM + i0t + seg * 8]);
        }
        CP_COMMIT();
    };

    // ---- prologue: hr table (once per CTA), then 3-deep chunk lookahead ----
    #pragma unroll
    for (int k = 0; k < 5; k++) {
        int m = tid + k * 256;
        if (m < HR_WORDS / 4) cp16(sbase + (uint32_t)m * 16, &g_hr[m * 4]);
    }
    CP_COMMIT();

    int kt_i = 0, ti = 0, qg = 0;
    #pragma unroll
    for (int s = 0; s < 3; s++) {
        if (kt_i < ntl) {
            issue_one(t_i0[kt_i], ti * KC, qg & 3);
            qg++;
            if (++ti == t_nT[kt_i]) { ti = 0; kt_i++; }
        } else CP_COMMIT();
    }

    float c[4][4][4];
    #pragma unroll
    for (int mt = 0; mt < 4; mt++)
        #pragma unroll
        for (int nt = 0; nt < 4; nt++)
            #pragma unroll
            for (int q = 0; q < 4; q++) c[mt][nt][q] = 0.f;

    const uint32_t b_row = (uint32_t)((lane & 7) + ((lane >> 3) & 1) * 8) * B_STRIDE
                         + (uint32_t)(wx * 32 + (lane >> 4) * 8) * 2;
    const int wlane = -(wy * 64 + (lane >> 2)) + 2 * (lane & 3);
    const float h0 = __ldg(&h[0]);

    int kt_c = 0, tc = 0;
    int j0 = t_j0[0], i0 = t_i0[0], nTc = t_nT[0];

    for (int pg = 0; pg < T_tot; pg++) {
        CP_WAIT2();
        __syncthreads();
        if (kt_i < ntl) {
            issue_one(t_i0[kt_i], ti * KC, qg & 3);
            qg++;
            if (++ti == t_nT[kt_i]) { ti = 0; kt_i++; }
        } else CP_COMMIT();

        // A words from reversed pair-packed h table
        uint32_t w[15];
        const int wb = NN - 1 - j0 + wlane - 56 + tc * KC;
        #pragma unroll
        for (int s = 0; s < 15; s++) w[s] = hr[wb + 8 * s];

        const uint32_t bs = sbase + SM_B_OFF + (uint32_t)(pg & 3) * STAGE_B + b_row;
        #pragma unroll
        for (int ks = 0; ks < 4; ks++) {
            uint32_t Bf[2][4];
            #pragma unroll
            for (int np = 0; np < 2; np++)
                ldmat_x4_t(Bf[np], bs + (uint32_t)(ks * 16 * B_STRIDE + np * 32));
            #pragma unroll
            for (int mt = 0; mt < 4; mt++) {
                const int base = 2 * ks + 6 - 2 * mt;
                uint32_t a[4];
                a[0] = w[base + 1]; a[1] = w[base]; a[2] = w[base + 2]; a[3] = w[base + 1];
                #pragma unroll
                for (int nt = 0; nt < 4; nt++)
                    mma16816(c[mt][nt], a, &Bf[nt >> 1][(nt & 1) * 2]);
            }
        }

        // ---- tile boundary: epilogue + accumulator reset ----
        if (++tc == nTc) {
            float k0lo[4], k0hi[4];
            #pragma unroll
            for (int nt = 0; nt < 4; nt++) {
                const int i = i0 + wx * 32 + nt * 8 + (lane & 3) * 2;
                __half2 k0 = *(const __half2*)&g_Kh[i];
                k0lo[nt] = __low2float(k0);
                k0hi[nt] = __high2float(k0);
            }
            #pragma unroll
            for (int mt = 0; mt < 4; mt++) {
                #pragma unroll
                for (int hf = 0; hf < 2; hf++) {
                    const int j = j0 + wy * 64 + mt * 16 + (lane >> 2) + hf * 8;
                    const float fej = __ldg(&fe[j]);
                    const float hj  = __ldg(&h[j]);
                    #pragma unroll
                    for (int nt = 0; nt < 4; nt++) {
                        const int i = i0 + wx * 32 + nt * 8 + (lane & 3) * 2;
                        const size_t gi = (size_t)j * MM + i;
                        __half2 kj = *(const __half2*)&g_Kh[gi];
                        float* cc = c[mt][nt];
                        float2 o;
                        o.x = fej + DTC * (0.5f * k0lo[nt] * hj - 0.5f * __low2float(kj)  * h0 - cc[hf * 2 + 0]);
                        o.y = fej + DTC * (0.5f * k0hi[nt] * hj - 0.5f * __high2float(kj) * h0 - cc[hf * 2 + 1]);
                        *(float2*)&out[gi] = o;
                    }
                }
            }
            #pragma unroll
            for (int mt = 0; mt < 4; mt++)
                #pragma unroll
                for (int nt = 0; nt < 4; nt++)
                    #pragma unroll
                    for (int q = 0; q < 4; q++) c[mt][nt][q] = 0.f;
            tc = 0;
            kt_c++;
            if (kt_c < ntl) { j0 = t_j0[kt_c]; i0 = t_i0[kt_c]; nTc = t_nT[kt_c]; }
        }
    }
}

extern "C" void kernel_launch(void* const* d_in, const int* in_sizes, int n_in,
                              void* d_out, int out_size) {
    const float* x  = (const float*)d_in[0];
    const float* fe = (const float*)d_in[1];
    const float* h  = (const float*)d_in[2];
    float* out = (float*)d_out;

    cudaFuncSetAttribute(memint_mma, cudaFuncAttributeMaxDynamicSharedMemorySize, SMEM_TOTAL);

    exp_kernel<<<8192, 256>>>(x);
    pack_hr_kernel<<<(HR_WORDS + 255) / 256, 256>>>(h);

    memint_mma<<<NCTA, 256, SMEM_TOTAL>>>(fe, h, out);
}

// round 12
// speedup vs baseline: 1.6716x; 1.6716x over previous
#include <cuda_runtime.h>
#include <cuda_fp16.h>
#include <cstdint>

#define NN 4096
#define MM 4096
#define DTC 0.01f

__device__ __half g_Kh[(size_t)NN * MM];

#define HR_WORDS (NN + 256)
__device__ __align__(16) uint32_t g_hr[HR_WORDS];

__global__ void exp_kernel(const float* __restrict__ x) {
    size_t p = (size_t)blockIdx.x * blockDim.x + threadIdx.x;
    float4 v = ((const float4*)x)[p];
    __half2 a = __floats2half2_rn(expf(-v.x), expf(-v.y));
    __half2 b = __floats2half2_rn(expf(-v.z), expf(-v.w));
    uint2 w;
    w.x = *(uint32_t*)&a;
    w.y = *(uint32_t*)&b;
    ((uint2*)g_Kh)[p] = w;
}

// g_hr[v] = (h[NN-1-v], h[NN-2-v]) as half2; zero-padded past the end (causal mask)
__global__ void pack_hr_kernel(const float* __restrict__ h) {
    int v = blockIdx.x * blockDim.x + threadIdx.x;
    if (v >= HR_WORDS) return;
    float e0 = (v < NN)     ? h[NN - 1 - v] : 0.f;
    float e1 = (v + 1 < NN) ? h[NN - 2 - v] : 0.f;
    __half2 p = __floats2half2_rn(e0, e1);
    g_hr[v] = *(uint32_t*)&p;
}

// ---------------- smem layout ----------------
#define SM_B_OFF (HR_WORDS * 4)        // 17408 bytes
#define B_STRIDE 272                   // 128 halfs + 8 pad
#define KC 64                          // K-chunk
#define STAGE_B  (KC * B_STRIDE)       // 17408
#define NSTAGE   4
#define SMEM_TOTAL (SM_B_OFF + NSTAGE * STAGE_B)   // 87040

__device__ __forceinline__ uint32_t smem_u32(const void* p) {
    return (uint32_t)__cvta_generic_to_shared(p);
}
__device__ __forceinline__ void cp16(uint32_t dst, const void* src) {
    asm volatile("cp.async.cg.shared.global [%0], [%1], 16;" :: "r"(dst), "l"(src) : "memory");
}
#define CP_COMMIT() asm volatile("cp.async.commit_group;" ::: "memory")
#define CP_WAIT2()  asm volatile("cp.async.wait_group 2;" ::: "memory")

__device__ __forceinline__ void ldmat_x4_t(uint32_t* r, uint32_t addr) {
    asm volatile("ldmatrix.sync.aligned.m8n8.x4.trans.shared.b16 {%0,%1,%2,%3}, [%4];"
                 : "=r"(r[0]), "=r"(r[1]), "=r"(r[2]), "=r"(r[3]) : "r"(addr));
}
__device__ __forceinline__ void mma16816(float* c, const uint32_t* a, const uint32_t* b) {
    asm volatile("mma.sync.aligned.m16n8k16.row.col.f32.f16.f16.f32 "
                 "{%0,%1,%2,%3}, {%4,%5,%6,%7}, {%8,%9}, {%0,%1,%2,%3};"
                 : "+f"(c[0]), "+f"(c[1]), "+f"(c[2]), "+f"(c[3])
                 : "r"(a[0]), "r"(a[1]), "r"(a[2]), "r"(a[3]), "r"(b[0]), "r"(b[1]));
}

// CTA tile 128(j) x 128(i), 8 warps of 64(j) x 32(i): wy 0..1, wx 0..3.
// K-chunk 64 (4 x k16). A fragments directly from reversed pair-packed h table.
__global__ __launch_bounds__(256, 2) void memint_mma(
    const float* __restrict__ fe,
    const float* __restrict__ h,
    float* __restrict__ out)
{
    extern __shared__ char smem[];
    const uint32_t sbase = smem_u32(smem);
    uint32_t* hr = (uint32_t*)smem;

    const int tid  = threadIdx.x;
    const int lane = tid & 31;
    const int wid  = tid >> 5;
    const int wy   = wid & 1;       // j half (64)
    const int wx   = wid >> 1;      // i quarter (32)
    const int i0 = blockIdx.x * 128;
    const int j0 = ((int)gridDim.y - 1 - (int)blockIdx.y) * 128;   // heavy tiles first

    const int numT = (j0 >> 6) + 2;

    auto issue_B = [&](int t) {
        const int l0 = t * KC;
        const uint32_t bs = sbase + SM_B_OFF + (uint32_t)(t & 3) * STAGE_B;
        #pragma unroll
        for (int k = 0; k < 4; k++) {
            int m = tid + k * 256;       // 1024 16B segments
            int row = m >> 4;            // l row 0..63
            int seg = m & 15;
            cp16(bs + (uint32_t)(row * B_STRIDE + seg * 16),
                 &g_Kh[(size_t)(l0 + row) * MM + i0 + seg * 8]);
        }
        CP_COMMIT();
    };

    // prologue: hr table via cp.async, then 3-deep B lookahead
    #pragma unroll
    for (int k = 0; k < 5; k++) {
        int m = tid + k * 256;
        if (m < HR_WORDS / 4) cp16(sbase + (uint32_t)m * 16, &g_hr[m * 4]);
    }
    CP_COMMIT();
    #pragma unroll
    for (int s = 0; s < 3; s++) {
        if (s < numT) issue_B(s); else CP_COMMIT();
    }

    float c[4][4][4];
    #pragma unroll
    for (int mt = 0; mt < 4; mt++)
        #pragma unroll
        for (int nt = 0; nt < 4; nt++)
            #pragma unroll
            for (int q = 0; q < 4; q++) c[mt][nt][q] = 0.f;

    const uint32_t b_row = (uint32_t)((lane & 7) + ((lane >> 3) & 1) * 8) * B_STRIDE
                         + (uint32_t)(wx * 32 + (lane >> 4) * 8) * 2;
    // lv[mt][q] = hr[vb - mt*16 - 8 + 8q] = w[q + 6 - 2mt], w[s] = hr[vb - 56 + 8s], s=0..14
    const int wbase0 = NN - 1 - (j0 + wy * 64 + (lane >> 2)) + 2 * (lane & 3) - 56;

    for (int t = 0; t < numT; t++) {
        CP_WAIT2();
        __syncthreads();
        if (t + 3 < numT) issue_B(t + 3); else CP_COMMIT();

        uint32_t w[15];
        const int wb = wbase0 + t * KC;
        #pragma unroll
        for (int s = 0; s < 15; s++) w[s] = hr[wb + 8 * s];

        const uint32_t bs = sbase + SM_B_OFF + (uint32_t)(t & 3) * STAGE_B + b_row;
        #pragma unroll
        for (int ks = 0; ks < 4; ks++) {
            uint32_t Bf[2][4];
            #pragma unroll
            for (int np = 0; np < 2; np++)
                ldmat_x4_t(Bf[np], bs + (uint32_t)(ks * 16 * B_STRIDE + np * 32));
            #pragma unroll
            for (int mt = 0; mt < 4; mt++) {
                const int base = 2 * ks + 6 - 2 * mt;
                uint32_t a[4];
                a[0] = w[base + 1]; a[1] = w[base]; a[2] = w[base + 2]; a[3] = w[base + 1];
                #pragma unroll
                for (int nt = 0; nt < 4; nt++)
                    mma16816(c[mt][nt], a, &Bf[nt >> 1][(nt & 1) * 2]);
            }
        }
    }

    // ---- epilogue ----
    const float h0 = __ldg(&h[0]);
    float k0lo[4], k0hi[4];
    #pragma unroll
    for (int nt = 0; nt < 4; nt++) {
        const int i = i0 + wx * 32 + nt * 8 + (lane & 3) * 2;
        __half2 k0 = *(const __half2*)&g_Kh[i];
        k0lo[nt] = __low2float(k0);
        k0hi[nt] = __high2float(k0);
    }
    #pragma unroll
    for (int mt = 0; mt < 4; mt++) {
        #pragma unroll
        for (int hf = 0; hf < 2; hf++) {
            const int j = j0 + wy * 64 + mt * 16 + (lane >> 2) + hf * 8;
            const float fej = __ldg(&fe[j]);
            const float hj  = __ldg(&h[j]);
            #pragma unroll
            for (int nt = 0; nt < 4; nt++) {
                const int i = i0 + wx * 32 + nt * 8 + (lane & 3) * 2;
                const size_t gi = (size_t)j * MM + i;
                __half2 kj = *(const __half2*)&g_Kh[gi];
                const float* cc = c[mt][nt];
                float2 o;
                o.x = fej + DTC * (0.5f * k0lo[nt] * hj - 0.5f * __low2float(kj)  * h0 - cc[hf * 2 + 0]);
                o.y = fej + DTC * (0.5f * k0hi[nt] * hj - 0.5f * __high2float(kj) * h0 - cc[hf * 2 + 1]);
                *(float2*)&out[gi] = o;
            }
        }
    }
}

extern "C" void kernel_launch(void* const* d_in, const int* in_sizes, int n_in,
                              void* d_out, int out_size) {
    const float* x  = (const float*)d_in[0];
    const float* fe = (const float*)d_in[1];
    const float* h  = (const float*)d_in[2];
    float* out = (float*)d_out;

    cudaFuncSetAttribute(memint_mma, cudaFuncAttributeMaxDynamicSharedMemorySize, SMEM_TOTAL);

    exp_kernel<<<((size_t)NN * MM) / 4 / 256, 256>>>(x);
    pack_hr_kernel<<<(HR_WORDS + 255) / 256, 256>>>(h);

    dim3 grid(MM / 128, NN / 128);
    memint_mma<<<grid, 256, SMEM_TOTAL>>>(fe, h, out);
}

// round 15
// speedup vs baseline: 1.7989x; 1.0761x over previous
#include <cuda_runtime.h>
#include <cuda_fp16.h>
#include <cstdint>

#define NN 4096
#define MM 4096
#define DTC 0.01f

__device__ __half g_Kh[(size_t)NN * MM];

#define HR_WORDS (NN + 256)
__device__ __align__(16) uint32_t g_hr[HR_WORDS];

// exp + (block 0) hr-pack fused
__global__ void exp_kernel(const float* __restrict__ x, const float* __restrict__ h) {
    size_t p = (size_t)blockIdx.x * blockDim.x + threadIdx.x;
    float4 v = ((const float4*)x)[p];
    __half2 a = __floats2half2_rn(expf(-v.x), expf(-v.y));
    __half2 b = __floats2half2_rn(expf(-v.z), expf(-v.w));
    uint2 w;
    w.x = *(uint32_t*)&a;
    w.y = *(uint32_t*)&b;
    ((uint2*)g_Kh)[p] = w;

    if (blockIdx.x == 0) {
        for (int v2 = threadIdx.x; v2 < HR_WORDS; v2 += 256) {
            float e0 = (v2 < NN)     ? h[NN - 1 - v2] : 0.f;
            float e1 = (v2 + 1 < NN) ? h[NN - 2 - v2] : 0.f;
            __half2 pk = __floats2half2_rn(e0, e1);
            g_hr[v2] = *(uint32_t*)&pk;
        }
    }
}

// ---------------- smem layout ----------------
#define SM_B_OFF (HR_WORDS * 4)        // 17408 bytes
#define B_STRIDE 272                   // 128 halfs + 8 pad
#define KC 64                          // K-chunk
#define STAGE_B  (KC * B_STRIDE)       // 17408
#define NSTAGE   4
#define SMEM_TOTAL (SM_B_OFF + NSTAGE * STAGE_B)   // 87040

__device__ __forceinline__ uint32_t smem_u32(const void* p) {
    return (uint32_t)__cvta_generic_to_shared(p);
}
__device__ __forceinline__ void cp16(uint32_t dst, const void* src) {
    asm volatile("cp.async.cg.shared.global [%0], [%1], 16;" :: "r"(dst), "l"(src) : "memory");
}
#define CP_COMMIT() asm volatile("cp.async.commit_group;" ::: "memory")
#define CP_WAIT2()  asm volatile("cp.async.wait_group 2;" ::: "memory")
#define CP_WAIT3()  asm volatile("cp.async.wait_group 3;" ::: "memory")
#define BAR_PAIR(id) asm volatile("bar.sync %0, 64;" :: "r"(id) : "memory")

__device__ __forceinline__ void ldmat_x4_t(uint32_t* r, uint32_t addr) {
    asm volatile("ldmatrix.sync.aligned.m8n8.x4.trans.shared.b16 {%0,%1,%2,%3}, [%4];"
                 : "=r"(r[0]), "=r"(r[1]), "=r"(r[2]), "=r"(r[3]) : "r"(addr));
}
__device__ __forceinline__ void mma16816(float* c, const uint32_t* a, const uint32_t* b) {
    asm volatile("mma.sync.aligned.m16n8k16.row.col.f32.f16.f16.f32 "
                 "{%0,%1,%2,%3}, {%4,%5,%6,%7}, {%8,%9}, {%0,%1,%2,%3};"
                 : "+f"(c[0]), "+f"(c[1]), "+f"(c[2]), "+f"(c[3])
                 : "r"(a[0]), "r"(a[1]), "r"(a[2]), "r"(a[3]), "r"(b[0]), "r"(b[1]));
}

// CTA tile 128(j) x 128(i), 8 warps of 64(j) x 32(i): wy 0..1, wx 0..3.
// Warp-pair-local B staging: each wx pair cp.asyncs ONLY its 32-i slice and
// syncs with a 64-thread named barrier — pairs run decoupled through chunks.
__global__ __launch_bounds__(256, 2) void memint_mma(
    const float* __restrict__ fe,
    const float* __restrict__ h,
    float* __restrict__ out)
{
    extern __shared__ char smem[];
    const uint32_t sbase = smem_u32(smem);
    uint32_t* hr = (uint32_t*)smem;

    const int tid  = threadIdx.x;
    const int lane = tid & 31;
    const int wid  = tid >> 5;
    const int wy   = wid & 1;       // j half (64)
    const int wx   = wid >> 1;      // i quarter (32)
    const int pu   = tid & 63;      // thread index within the wx pair
    const int i0 = blockIdx.x * 128;
    const int j0 = ((int)gridDim.y - 1 - (int)blockIdx.y) * 128;   // heavy tiles first

    const int numT = (j0 >> 6) + 2;

    // per-pair B issue: 64 rows x 4 segs (16B) of this pair's 32-i slice
    auto issue_B = [&](int t) {
        const int l0 = t * KC;
        const uint32_t bs = sbase + SM_B_OFF + (uint32_t)(t & 3) * STAGE_B;
        const int sq = pu & 3;                 // seg within quarter
        const int rb = pu >> 2;                // row base 0..15
        #pragma unroll
        for (int k = 0; k < 4; k++) {
            int row = (k << 4) | rb;           // 0..63
            cp16(bs + (uint32_t)(row * B_STRIDE + (wx * 4 + sq) * 16),
                 &g_Kh[(size_t)(l0 + row) * MM + i0 + wx * 32 + sq * 8]);
        }
        CP_COMMIT();
    };

    // prologue: hr table (CTA-shared), then 3-deep per-pair B lookahead
    #pragma unroll
    for (int k = 0; k < 5; k++) {
        int m = tid + k * 256;
        if (m < HR_WORDS / 4) cp16(sbase + (uint32_t)m * 16, &g_hr[m * 4]);
    }
    CP_COMMIT();
    #pragma unroll
    for (int s = 0; s < 3; s++) {
        if (s < numT) issue_B(s); else CP_COMMIT();
    }
    CP_WAIT3();           // hr group drained
    __syncthreads();      // hr visible CTA-wide (one-time)

    float c[4][4][4];
    #pragma unroll
    for (int mt = 0; mt < 4; mt++)
        #pragma unroll
        for (int nt = 0; nt < 4; nt++)
            #pragma unroll
            for (int q = 0; q < 4; q++) c[mt][nt][q] = 0.f;

    const uint32_t b_row = (uint32_t)((lane & 7) + ((lane >> 3) & 1) * 8) * B_STRIDE
                         + (uint32_t)(wx * 32 + (lane >> 4) * 8) * 2;
    // lv[mt][q] = hr[vb - mt*16 - 8 + 8q] = w[q + 6 - 2mt], w[s] = hr[vb - 56 + 8s]
    const int wbase0 = NN - 1 - (j0 + wy * 64 + (lane >> 2)) + 2 * (lane & 3) - 56;
    const int barid = wx + 1;

    for (int t = 0; t < numT; t++) {
        CP_WAIT2();
        BAR_PAIR(barid);
        if (t + 3 < numT) issue_B(t + 3); else CP_COMMIT();

        uint32_t w[15];
        const int wb = wbase0 + t * KC;
        #pragma unroll
        for (int s = 0; s < 15; s++) w[s] = hr[wb + 8 * s];

        const uint32_t bs = sbase + SM_B_OFF + (uint32_t)(t & 3) * STAGE_B + b_row;
        #pragma unroll
        for (int ks = 0; ks < 4; ks++) {
            uint32_t Bf[2][4];
            #pragma unroll
            for (int np = 0; np < 2; np++)
                ldmat_x4_t(Bf[np], bs + (uint32_t)(ks * 16 * B_STRIDE + np * 32));
            #pragma unroll
            for (int mt = 0; mt < 4; mt++) {
                const int base = 2 * ks + 6 - 2 * mt;
                uint32_t a[4];
                a[0] = w[base + 1]; a[1] = w[base]; a[2] = w[base + 2]; a[3] = w[base + 1];
                #pragma unroll
                for (int nt = 0; nt < 4; nt++)
                    mma16816(c[mt][nt], a, &Bf[nt >> 1][(nt & 1) * 2]);
            }
        }
    }

    // ---- epilogue (per-warp independent) ----
    const float h0 = __ldg(&h[0]);
    float k0lo[4], k0hi[4];
    #pragma unroll
    for (int nt = 0; nt < 4; nt++) {
        const int i = i0 + wx * 32 + nt * 8 + (lane & 3) * 2;
        __half2 k0 = *(const __half2*)&g_Kh[i];
        k0lo[nt] = __low2float(k0);
        k0hi[nt] = __high2float(k0);
    }
    #pragma unroll
    for (int mt = 0; mt < 4; mt++) {
        #pragma unroll
        for (int hf = 0; hf < 2; hf++) {
            const int j = j0 + wy * 64 + mt * 16 + (lane >> 2) + hf * 8;
            const float fej = __ldg(&fe[j]);
            const float hj  = __ldg(&h[j]);
            #pragma unroll
            for (int nt = 0; nt < 4; nt++) {
                const int i = i0 + wx * 32 + nt * 8 + (lane & 3) * 2;
                const size_t gi = (size_t)j * MM + i;
                __half2 kj = *(const __half2*)&g_Kh[gi];
                const float* cc = c[mt][nt];
                float2 o;
                o.x = fej + DTC * (0.5f * k0lo[nt] * hj - 0.5f * __low2float(kj)  * h0 - cc[hf * 2 + 0]);
                o.y = fej + DTC * (0.5f * k0hi[nt] * hj - 0.5f * __high2float(kj) * h0 - cc[hf * 2 + 1]);
                *(float2*)&out[gi] = o;
            }
        }
    }
}

extern "C" void kernel_launch(void* const* d_in, const int* in_sizes, int n_in,
                              void* d_out, int out_size) {
    const float* x  = (const float*)d_in[0];
    const float* fe = (const float*)d_in[1];
    const float* h  = (const float*)d_in[2];
    float* out = (float*)d_out;

    cudaFuncSetAttribute(memint_mma, cudaFuncAttributeMaxDynamicSharedMemorySize, SMEM_TOTAL);

    exp_kernel<<<((size_t)NN * MM) / 4 / 256, 256>>>(x, h);

    dim3 grid(MM / 128, NN / 128);
    memint_mma<<<grid, 256, SMEM_TOTAL>>>(fe, h, out);
}